// round 16
// baseline (speedup 1.0000x reference)
#include <cuda_runtime.h>
#include <math.h>

#define B_    64
#define S_    196
#define DM    1024
#define DI    512
#define MEMN  25
#define ITERS 50
#define OUTN  1000
#define MS    (B_*S_)
#define NB    256

#define OFF_CERT (B_*OUTN*ITERS)
#define OFF_SYNC (OFF_CERT + B_*2*ITERS)

// ------------------------- device scratch ----------------------------------
__device__ __align__(16) float g_kv   [MS*DI];
__device__ __align__(16) float g_KV   [MS*DM];
__device__ __align__(16) float g_Wqkv [3*DM*DM];
__device__ __align__(16) float g_Mq   [DI*DM];
__device__ __align__(16) float g_beff [DI];
__device__ __align__(16) float g_synw2[2048*1536];
__device__ __align__(16) float g_bsyn [2048];
__device__ __align__(16) float g_Qb   [B_*MEMN*DM];
__device__ __align__(16) float g_Kb   [B_*MEMN*DM];
__device__ __align__(16) float g_st   [MEMN*DM*B_];
__device__ __align__(16) float g_act  [B_*DM];
__device__ __align__(16) float g_sync [B_*DM];
__device__ __align__(16) float g_pre2 [B_*1536];
__device__ __align__(16) float g_Pq   [8*B_*DI];
__device__ __align__(16) float g_Po   [8*B_*OUTN];
__device__ __align__(16) float g_Ps   [12*B_*2048];
__device__ __align__(16) float g_Pk   [8*B_*3*DM];
__device__ unsigned g_barCnt;

// ------------------------- fast exp (FMA pipe, not MUFU) -------------------
__device__ __forceinline__ float fexp(float x){
    x = fminf(fmaxf(x,-80.f),80.f);
    float y = x*1.442695041f;
    float n = rintf(y);
    float f = y - n;
    float p = 1.3333558e-3f;
    p = fmaf(p,f,9.6181250e-3f);
    p = fmaf(p,f,5.5504110e-2f);
    p = fmaf(p,f,2.4022650e-1f);
    p = fmaf(p,f,6.9314718e-1f);
    p = fmaf(p,f,1.0f);
    return __int_as_float(__float_as_int(p) + (((int)n)<<23));
}
__device__ __forceinline__ float sigm(float x){ return 1.f/(1.f+fexp(-x)); }

// ------------------------- tf32 mma + hi/lo split ---------------------------
__device__ __forceinline__ unsigned f2tf(float x){
    unsigned r; asm("cvt.rna.tf32.f32 %0, %1;" : "=r"(r) : "f"(x)); return r;
}
__device__ __forceinline__ void split_tf(float v, unsigned &hi, unsigned &lo){
    hi = f2tf(v);
    lo = f2tf(v - __uint_as_float(hi));
}
__device__ __forceinline__ void mma_tf32(float* c,
        unsigned a0,unsigned a1,unsigned a2,unsigned a3,
        unsigned b0,unsigned b1){
    asm volatile("mma.sync.aligned.m16n8k8.row.col.f32.tf32.tf32.f32 "
        "{%0,%1,%2,%3}, {%4,%5,%6,%7}, {%8,%9}, {%0,%1,%2,%3};"
        : "+f"(c[0]),"+f"(c[1]),"+f"(c[2]),"+f"(c[3])
        : "r"(a0),"r"(a1),"r"(a2),"r"(a3),"r"(b0),"r"(b1));
}

// ------------------------- reductions --------------------------------------
__device__ __forceinline__ float warpSum(float v){
    #pragma unroll
    for(int o=16;o;o>>=1) v += __shfl_down_sync(0xffffffffu,v,o);
    return v;
}
__device__ __forceinline__ float warpMax(float v){
    #pragma unroll
    for(int o=16;o;o>>=1) v = fmaxf(v,__shfl_down_sync(0xffffffffu,v,o));
    return v;
}
__device__ float blockSum(float v, float* buf){
    int lane=threadIdx.x&31, w=threadIdx.x>>5, nw=(blockDim.x+31)>>5;
    v=warpSum(v);
    if(lane==0) buf[w]=v;
    __syncthreads();
    v=(threadIdx.x<nw)?buf[threadIdx.x]:0.f;
    if(w==0) v=warpSum(v);
    if(threadIdx.x==0) buf[0]=v;
    __syncthreads();
    float r=buf[0]; __syncthreads(); return r;
}
__device__ float blockMax(float v, float* buf){
    int lane=threadIdx.x&31, w=threadIdx.x>>5, nw=(blockDim.x+31)>>5;
    v=warpMax(v);
    if(lane==0) buf[w]=v;
    __syncthreads();
    v=(threadIdx.x<nw)?buf[threadIdx.x]:-1e30f;
    if(w==0) v=warpMax(v);
    if(threadIdx.x==0) buf[0]=v;
    __syncthreads();
    float r=buf[0]; __syncthreads(); return r;
}

// ------------------------- grid barrier ------------------------------------
__device__ __forceinline__ void gsync(unsigned &target){
    __threadfence();
    __syncthreads();
    target += NB;
    if(threadIdx.x==0){
        atomicAdd(&g_barCnt,1u);
        while(*(volatile unsigned*)&g_barCnt < target) __nanosleep(64);
        __threadfence();
    }
    __syncthreads();
}

// ======================= 3xTF32 GEMM unit ===================================
// A: 64 x Ksrc rm. W: N x Ksrc rm (computes A @ W^T).
// 64x128 output tile at cols [n0,n0+128) over K-slab z (ksteps*16).
// Writes P[(z*64+m)*N + n]  (+bias if given). Near-fp32 via hi/lo split.
#define AS_STRIDE 68
#define BS_STRIDE 132
__device__ void unit_gemm_tc(const float* __restrict__ A,const float* __restrict__ W,
                             float* __restrict__ P,const float* __restrict__ bias,
                             int N,int Ksrc,int n0,int z,int ksteps,float* sm){
    float* As=sm;            // 2 x 16 x 68
    float* Bs=sm+2176;       // 2 x 16 x 132
    const int tid=threadIdx.x;
    const int ar=tid>>2, ac=(tid&3)*4;
    const int br=tid>>1, bc=(tid&1)*8;
    const int k0=z*ksteps*16;
    const bool wok=(n0+br)<N;
    const float* Ap=A+(size_t)ar*Ksrc + k0 + ac;
    const float* Wp=W+(size_t)(n0+br)*Ksrc + k0 + bc;
    const int w=tid>>5, lane=tid&31;
    const int mw=(w&1)*32, nw=(w>>1)*32;
    const int gid=lane>>2, tg=lane&3;
    float c[2][4][4];
    #pragma unroll
    for(int i=0;i<2;i++)
        #pragma unroll
        for(int j=0;j<4;j++){c[i][j][0]=0;c[i][j][1]=0;c[i][j][2]=0;c[i][j][3]=0;}
    float4 a=*(const float4*)Ap;
    float4 b0v=wok?*(const float4*)Wp:make_float4(0,0,0,0);
    float4 b1v=wok?*(const float4*)(Wp+4):make_float4(0,0,0,0);
    __syncthreads();                     // drain previous unit's smem use
    for(int s=0;s<ksteps;s++){
        float* Ab=As+(s&1)*1088;
        float* Bb=Bs+(s&1)*2112;
        Ab[(ac+0)*AS_STRIDE+ar]=a.x; Ab[(ac+1)*AS_STRIDE+ar]=a.y;
        Ab[(ac+2)*AS_STRIDE+ar]=a.z; Ab[(ac+3)*AS_STRIDE+ar]=a.w;
        Bb[(bc+0)*BS_STRIDE+br]=b0v.x; Bb[(bc+1)*BS_STRIDE+br]=b0v.y;
        Bb[(bc+2)*BS_STRIDE+br]=b0v.z; Bb[(bc+3)*BS_STRIDE+br]=b0v.w;
        Bb[(bc+4)*BS_STRIDE+br]=b1v.x; Bb[(bc+5)*BS_STRIDE+br]=b1v.y;
        Bb[(bc+6)*BS_STRIDE+br]=b1v.z; Bb[(bc+7)*BS_STRIDE+br]=b1v.w;
        __syncthreads();
        if(s+1<ksteps){
            a=*(const float4*)(Ap+(s+1)*16);
            b0v=wok?*(const float4*)(Wp+(s+1)*16):make_float4(0,0,0,0);
            b1v=wok?*(const float4*)(Wp+(s+1)*16+4):make_float4(0,0,0,0);
        }
        #pragma unroll
        for(int kb=0;kb<16;kb+=8){
            unsigned ah[2][4], al[2][4];
            #pragma unroll
            for(int mf=0;mf<2;mf++){
                int mb=mw+mf*16;
                split_tf(Ab[(kb+tg  )*AS_STRIDE + mb+gid  ], ah[mf][0], al[mf][0]);
                split_tf(Ab[(kb+tg  )*AS_STRIDE + mb+gid+8], ah[mf][1], al[mf][1]);
                split_tf(Ab[(kb+tg+4)*AS_STRIDE + mb+gid  ], ah[mf][2], al[mf][2]);
                split_tf(Ab[(kb+tg+4)*AS_STRIDE + mb+gid+8], ah[mf][3], al[mf][3]);
            }
            #pragma unroll
            for(int nf=0;nf<4;nf++){
                int nb=nw+nf*8;
                unsigned bh0,bl0,bh1,bl1;
                split_tf(Bb[(kb+tg  )*BS_STRIDE + nb+gid], bh0,bl0);
                split_tf(Bb[(kb+tg+4)*BS_STRIDE + nb+gid], bh1,bl1);
                mma_tf32(c[0][nf],ah[0][0],ah[0][1],ah[0][2],ah[0][3],bh0,bh1);
                mma_tf32(c[1][nf],ah[1][0],ah[1][1],ah[1][2],ah[1][3],bh0,bh1);
                mma_tf32(c[0][nf],al[0][0],al[0][1],al[0][2],al[0][3],bh0,bh1);
                mma_tf32(c[1][nf],al[1][0],al[1][1],al[1][2],al[1][3],bh0,bh1);
                mma_tf32(c[0][nf],ah[0][0],ah[0][1],ah[0][2],ah[0][3],bl0,bl1);
                mma_tf32(c[1][nf],ah[1][0],ah[1][1],ah[1][2],ah[1][3],bl0,bl1);
            }
        }
        __syncthreads();
    }
    float* Pb=P+((size_t)z*64)*N + n0;
    #pragma unroll
    for(int mf=0;mf<2;mf++){
        #pragma unroll
        for(int nf=0;nf<4;nf++){
            int m0r=mw+mf*16+gid;
            int nn=nw+nf*8+tg*2;
            float v0=c[mf][nf][0],v1=c[mf][nf][1],v2=c[mf][nf][2],v3=c[mf][nf][3];
            if(bias && n0+nn<N){ v0+=bias[n0+nn]; v2+=bias[n0+nn]; }
            if(bias && n0+nn+1<N){ v1+=bias[n0+nn+1]; v3+=bias[n0+nn+1]; }
            if(n0+nn<N){
                Pb[(size_t)m0r*N+nn]=v0;
                Pb[(size_t)(m0r+8)*N+nn]=v2;
            }
            if(n0+nn+1<N){
                Pb[(size_t)m0r*N+nn+1]=v1;
                Pb[(size_t)(m0r+8)*N+nn+1]=v3;
            }
        }
    }
}

// standalone wrapper for setup GEMMs (M multiple of 64)
__global__ void __launch_bounds__(256) k_gemm_tc(const float* __restrict__ A,
                                                 const float* __restrict__ W,
                                                 float* __restrict__ C,
                                                 const float* __restrict__ bias,
                                                 int N,int K){
    __shared__ float sm[6400];
    unit_gemm_tc(A + (size_t)blockIdx.y*64*K, W,
                 C + (size_t)blockIdx.y*64*N, bias,
                 N, K, blockIdx.x*128, 0, K/16, sm);
}

// ------------------------- setup: TN GEMM C = A(MxK)@B(KxN), fp32 ----------
__global__ void __launch_bounds__(256) k_gemm_tn(const float* __restrict__ A,
                                                 const float* __restrict__ B,
                                                 float* __restrict__ C,
                                                 int lda,int ldb,int ldc,int K,int transC){
    __shared__ float As[16][64];
    __shared__ float Bs[16][64];
    const int n0=blockIdx.x*64, m0=blockIdx.y*64;
    const int tid=threadIdx.x;
    const int tx=tid&15, ty=tid>>4;
    const int lr=tid>>2, lc=tid&3;
    const int br=tid>>4, bc=(tid&15)*4;
    float c[4][4];
    #pragma unroll
    for(int i=0;i<4;i++){c[i][0]=0;c[i][1]=0;c[i][2]=0;c[i][3]=0;}
    for(int k0=0;k0<K;k0+=16){
        float4 av=*(const float4*)(A+(size_t)(m0+lr)*lda + k0 + lc*4);
        float4 bv=*(const float4*)(B+(size_t)(k0+br)*ldb + n0 + bc);
        __syncthreads();
        As[lc*4+0][lr]=av.x; As[lc*4+1][lr]=av.y; As[lc*4+2][lr]=av.z; As[lc*4+3][lr]=av.w;
        *(float4*)&Bs[br][bc]=bv;
        __syncthreads();
        #pragma unroll
        for(int q=0;q<16;q++){
            float4 a=*(const float4*)&As[q][ty*4];
            float4 w=*(const float4*)&Bs[q][tx*4];
            c[0][0]+=a.x*w.x; c[0][1]+=a.x*w.y; c[0][2]+=a.x*w.z; c[0][3]+=a.x*w.w;
            c[1][0]+=a.y*w.x; c[1][1]+=a.y*w.y; c[1][2]+=a.y*w.z; c[1][3]+=a.y*w.w;
            c[2][0]+=a.z*w.x; c[2][1]+=a.z*w.y; c[2][2]+=a.z*w.z; c[2][3]+=a.z*w.w;
            c[3][0]+=a.w*w.x; c[3][1]+=a.w*w.y; c[3][2]+=a.w*w.z; c[3][3]+=a.w*w.w;
        }
    }
    #pragma unroll
    for(int i=0;i<4;i++){
        #pragma unroll
        for(int j=0;j<4;j++){
            int m=m0+ty*4+i, n=n0+tx*4+j;
            if(transC) C[(size_t)n*ldc+m]=c[i][j];
            else       C[(size_t)m*ldc+n]=c[i][j];
        }
    }
}

// ------------------------- setup small kernels ------------------------------
__global__ void k_copyW(const float* __restrict__ wq,const float* __restrict__ wk,
                        const float* __restrict__ wv,float* __restrict__ dst){
    int i=blockIdx.x*blockDim.x+threadIdx.x;
    if(i>=3*DM*DM) return;
    int part=i/(DM*DM), r=i%(DM*DM);
    dst[i]=(part==0)?wq[r]:(part==1)?wk[r]:wv[r];
}
__global__ void k_copyW2(const float* __restrict__ synw,float* __restrict__ dst){
    int i=blockIdx.x*blockDim.x+threadIdx.x;
    if(i>=2048*1024) return;
    int m=i>>10, k=i&1023;
    dst[(size_t)m*1536+512+k]=synw[(size_t)m*1536+512+k];
}
__global__ void k_initact(const float* __restrict__ sas,float* __restrict__ act,
                          float* __restrict__ pre2){
    int i=blockIdx.x*blockDim.x+threadIdx.x;
    if(i>=B_*DM) return;
    float v=sas[i&(DM-1)];
    act[i]=v;
    pre2[(size_t)(i>>10)*1536 + 512 + (i&(DM-1))]=v;
}
__global__ void k_initst(const float* __restrict__ strace,float* __restrict__ st){
    int i=blockIdx.x*blockDim.x+threadIdx.x;
    if(i>=MEMN*DM*B_) return;
    int slot=i/(DM*B_), r=i%(DM*B_), d=r/B_;
    st[i]=strace[d*MEMN+slot];
}
__global__ void k_lnkv(const float* __restrict__ tmp,const float* __restrict__ kvb,
                       const float* __restrict__ lns,const float* __restrict__ lnb,
                       float* __restrict__ kv){
    __shared__ float red[33];
    int r=blockIdx.x, tid=threadIdx.x;
    float v0=tmp[r*DI+tid]+kvb[tid];
    float v1=tmp[r*DI+tid+256]+kvb[tid+256];
    float s=blockSum(v0+v1,red);
    float sq=blockSum(v0*v0+v1*v1,red);
    float mean=s*(1.f/DI);
    float var=sq*(1.f/DI)-mean*mean;
    float rstd=rsqrtf(var+1e-5f);
    kv[r*DI+tid]    =(v0-mean)*rstd*lns[tid]    +lnb[tid];
    kv[r*DI+tid+256]=(v1-mean)*rstd*lns[tid+256]+lnb[tid+256];
}
__global__ void k_bvec(const float* __restrict__ W,int lda,int K,
                       const float* __restrict__ v,const float* __restrict__ b0,
                       float* __restrict__ o,int n){
    int i=blockIdx.x*blockDim.x+threadIdx.x;
    if(i>=n) return;
    float a=b0[i];
    const float* wr=W+(size_t)i*lda;
    for(int k=0;k<K;k++) a+=wr[k]*v[k];
    o[i]=a;
}
__global__ void k_zero(unsigned* p){ if(threadIdx.x==0) *p=0; }

// ======================= other megakernel phase workers =====================
__device__ void unit_crossatt(int b,int h,const float* __restrict__ beff,
                              float* __restrict__ pre2,float* sm){
    float* q2s=sm;          // 64
    float* ws =sm+64;       // 196
    float* os =sm+260;      // 256
    float* red=sm+520;      // 33
    const int tid=threadIdx.x;
    __syncthreads();
    if(tid<64){
        float a=beff[h*64+tid];
        #pragma unroll
        for(int z=0;z<8;z++) a+=g_Pq[((size_t)z*64+b)*DI + h*64+tid];
        q2s[tid]=a;
    }
    __syncthreads();
    float sv=-1e30f;
    if(tid<S_){
        const float* kr=g_KV+((size_t)(b*S_+tid))*DM + h*64;
        float a=0.f;
        #pragma unroll 8
        for(int dd=0;dd<64;dd++) a+=q2s[dd]*kr[dd];
        sv=a*0.125f;
    }
    float mxv=blockMax(sv,red);
    float ev=(tid<S_)?fexp(sv-mxv):0.f;
    float Z=blockSum(ev,red);
    if(tid<S_) ws[tid]=ev/Z;
    __syncthreads();
    int dd=tid&63, part=tid>>6;
    float acc=0.f;
    for(int s=part*49;s<part*49+49;s++)
        acc+=ws[s]*g_KV[((size_t)(b*S_+s))*DM + DI + h*64 + dd];
    os[part*64+dd]=acc;
    __syncthreads();
    if(tid<64)
        pre2[(size_t)b*1536 + h*64 + tid]=os[tid]+os[64+tid]+os[128+tid]+os[192+tid];
}

__device__ void unit_pred(int b,const float* __restrict__ ob,
                          float* __restrict__ out,int t,float* sm){
    float* pv=sm;           // 1000
    float* red=sm+1000;     // 33
    const int tid=threadIdx.x;
    __syncthreads();
    float lmax=-1e30f;
    for(int j=tid;j<OUTN;j+=256){
        float v=ob[j];
        const float* p=g_Po+(size_t)b*OUTN + j;
        #pragma unroll
        for(int z=0;z<8;z++){ v+=p[0]; p+=(size_t)64*OUTN; }
        pv[j]=v;
        out[((size_t)b*OUTN+j)*ITERS+t]=v;
        lmax=fmaxf(lmax,v);
    }
    float mx=blockMax(lmax,red);
    float lz=0.f, ls1=0.f;
    for(int j=tid;j<OUTN;j+=256){
        float e=fexp(pv[j]-mx);
        lz+=e; ls1+=e*pv[j];
    }
    float Z=blockSum(lz,red);
    float S1=blockSum(ls1,red);
    if(tid==0){
        float logZ=logf(Z);
        float plogp=S1/Z - mx - logZ;
        float ne=-plogp*(1.f/logf((float)OUTN));
        out[OFF_CERT + ((size_t)b*2+0)*ITERS + t]=ne;
        out[OFF_CERT + ((size_t)b*2+1)*ITERS + t]=1.f-ne;
    }
}

__device__ void unit_synep(int b,const float* __restrict__ lns,
                           const float* __restrict__ lnb,int w,float* sm){
    float* vals=sm;         // 1024
    float* red=sm+1024;     // 33
    const int tid=threadIdx.x;
    __syncthreads();
    float s=0.f, sq=0.f;
    #pragma unroll
    for(int r=0;r<4;r++){
        int j=tid+r*256;
        float a=g_bsyn[j], g=g_bsyn[DM+j];
        const float* p=g_Ps+(size_t)b*2048 + j;
        #pragma unroll
        for(int z=0;z<12;z++){
            a+=p[0]; g+=p[DM];
            p+=(size_t)64*2048;
        }
        float v=a*sigm(g);
        vals[j]=v; s+=v; sq+=v*v;
    }
    s=blockSum(s,red); sq=blockSum(sq,red);
    float mean=s*(1.f/DM);
    float var=sq*(1.f/DM)-mean*mean;
    float rstd=rsqrtf(var+1e-5f);
    #pragma unroll
    for(int r=0;r<4;r++){
        int j=tid+r*256;
        g_st[((size_t)w*DM + j)*B_ + b]=(vals[j]-mean)*rstd*lns[j]+lnb[j];
    }
}

__device__ void unit_nlm(int u,const float* __restrict__ w1,const float* __restrict__ b1,
                         const float* __restrict__ w2,const float* __restrict__ b2,
                         int t,float* sm){
    float* w1s=sm;          // 3200
    float* b1s=sm+3200;     // 128
    float* w2s=sm+3328;     // 128
    float* b2s=sm+3456;     // 8
    const int tid=threadIdx.x, d0=u*4;
    __syncthreads();
    for(int i=tid;i<MEMN*32*4;i+=256){
        int m=i>>7, r=i&127, j=r>>2, dl=r&3;
        w1s[i]=w1[(size_t)(m*32+j)*DM + d0+dl];
    }
    if(tid<128){ int j=tid>>2, dl=tid&3; b1s[tid]=b1[(d0+dl)*32+j]; }
    else {
        int i=tid-128; int hh=i>>3, o=(i>>2)&1, dl=i&3;
        w2s[i]=w2[(size_t)(hh*2+o)*DM + d0+dl];
    }
    if(tid<8){ int o=tid>>2, dl=tid&3; b2s[tid]=b2[(d0+dl)*2+o]; }
    __syncthreads();
    int b=tid&63, dl=tid>>6, d=d0+dl;
    float stv[MEMN];
    #pragma unroll
    for(int m=0;m<MEMN;m++){
        int phys=(t+1+m)%MEMN;
        stv[m]=g_st[((size_t)phys*DM + d)*B_ + b];
    }
    float o0=0.f,o1=0.f;
    #pragma unroll
    for(int j=0;j<16;j++){
        float a=b1s[j*4+dl], g=b1s[(j+16)*4+dl];
        #pragma unroll
        for(int m=0;m<MEMN;m++){
            a+=stv[m]*w1s[(m*32+j)*4+dl];
            g+=stv[m]*w1s[(m*32+j+16)*4+dl];
        }
        float hv=a*sigm(g);
        o0+=hv*w2s[(j*2+0)*4+dl];
        o1+=hv*w2s[(j*2+1)*4+dl];
    }
    o0+=b2s[0*4+dl]; o1+=b2s[1*4+dl];
    float v=o0*sigm(o1);
    g_act[b*DM+d]=v;
    g_pre2[(size_t)b*1536 + 512 + d]=v;
}

// ======================= sync attention =====================================
// S = Q_ring^T (128x25) @ K_ring (25x128) via 3xTF32 MMA, fused online
// softmax + AV, no S materialization. Rings updated from QKV partials first.
#define RS 132
__device__ void unit_sync(int b,int h,int slot,int initAll,
                          float* __restrict__ outOpt,float* sm){
    float* Qs=sm;           // 32 x 132 (k=slot major)
    float* Ks=sm+4224;      // 32 x 132
    float* vn=sm+8448;      // 128
    const int tid=threadIdx.x;
    __syncthreads();
    // reduce QKV partials, update rings
    if(tid<128){
        int col=h*128+tid;
        float v=0.f;
        const float* p=g_Pk+(size_t)b*3072+col;
        #pragma unroll
        for(int z=0;z<8;z++){ v+=*p; p+=(size_t)64*3072; }
        if(initAll){
            #pragma unroll
            for(int m=0;m<MEMN;m++) g_Qb[(b*MEMN+m)*DM+col]=v;
        } else g_Qb[(b*MEMN+slot)*DM+col]=v;
    } else {
        int e=tid-128, col=h*128+e;
        float k=0.f, vv=0.f;
        const float* p=g_Pk+(size_t)b*3072+col;
        #pragma unroll
        for(int z=0;z<8;z++){ k+=p[1024]; vv+=p[2048]; p+=(size_t)64*3072; }
        vn[e]=vv;
        if(initAll){
            #pragma unroll
            for(int m=0;m<MEMN;m++) g_Kb[(b*MEMN+m)*DM+col]=k;
        } else g_Kb[(b*MEMN+slot)*DM+col]=k;
    }
    __syncthreads();   // ring writes visible block-wide
    // stage rings k-major (rows 25..31 zero)
    for(int i=tid;i<2048;i+=256){
        int mi=i&1023, row=mi>>5, c4=(mi&31)*4;
        float4 v=make_float4(0,0,0,0);
        if(row<MEMN){
            const float* src=(i<1024?g_Qb:g_Kb) + ((size_t)(b*MEMN+row))*DM + h*128 + c4;
            v=*(const float4*)src;
        }
        float* dst=(i<1024?Qs:Ks) + row*RS + c4;
        *(float4*)dst=v;
    }
    __syncthreads();
    // S-GEMM + online softmax + AV
    const int w=tid>>5, lane=tid&31;
    const int gid=lane>>2, tg=lane&3;
    const int mb=w*16;
    const float sc=0.08838834764831845f;   // 1/sqrt(128)
    float mA=-1e30f, ZA=0.f, AA=0.f;
    float mB=-1e30f, ZB=0.f, AB=0.f;
    #pragma unroll
    for(int half=0;half<2;half++){
        float c[8][4];
        #pragma unroll
        for(int nf=0;nf<8;nf++){c[nf][0]=0;c[nf][1]=0;c[nf][2]=0;c[nf][3]=0;}
        #pragma unroll
        for(int ks=0;ks<4;ks++){
            int kb=ks*8;
            unsigned ah[4],al[4];
            split_tf(Qs[(kb+tg  )*RS + mb+gid  ], ah[0], al[0]);
            split_tf(Qs[(kb+tg  )*RS + mb+gid+8], ah[1], al[1]);
            split_tf(Qs[(kb+tg+4)*RS + mb+gid  ], ah[2], al[2]);
            split_tf(Qs[(kb+tg+4)*RS + mb+gid+8], ah[3], al[3]);
            #pragma unroll
            for(int nf=0;nf<8;nf++){
                int nb=half*64+nf*8;
                unsigned bh0,bl0,bh1,bl1;
                split_tf(Ks[(kb+tg  )*RS + nb+gid], bh0,bl0);
                split_tf(Ks[(kb+tg+4)*RS + nb+gid], bh1,bl1);
                mma_tf32(c[nf],ah[0],ah[1],ah[2],ah[3],bh0,bh1);
                mma_tf32(c[nf],al[0],al[1],al[2],al[3],bh0,bh1);
                mma_tf32(c[nf],ah[0],ah[1],ah[2],ah[3],bl0,bl1);
            }
        }
        // online softmax/AV for this half's 64 cols
        float mhA=-1e30f, mhB=-1e30f;
        #pragma unroll
        for(int nf=0;nf<8;nf++){
            mhA=fmaxf(mhA,fmaxf(c[nf][0],c[nf][1]));
            mhB=fmaxf(mhB,fmaxf(c[nf][2],c[nf][3]));
        }
        mhA=fmaxf(mhA,__shfl_xor_sync(0xffffffffu,mhA,1));
        mhA=fmaxf(mhA,__shfl_xor_sync(0xffffffffu,mhA,2));
        mhB=fmaxf(mhB,__shfl_xor_sync(0xffffffffu,mhB,1));
        mhB=fmaxf(mhB,__shfl_xor_sync(0xffffffffu,mhB,2));
        float ZhA=0.f,AhA=0.f,ZhB=0.f,AhB=0.f;
        #pragma unroll
        for(int nf=0;nf<8;nf++){
            int col=half*64+nf*8+tg*2;
            float v0=vn[col], v1=vn[col+1];
            float e0=fexp((c[nf][0]-mhA)*sc), e1=fexp((c[nf][1]-mhA)*sc);
            ZhA+=e0+e1; AhA+=e0*v0+e1*v1;
            float f0=fexp((c[nf][2]-mhB)*sc), f1=fexp((c[nf][3]-mhB)*sc);
            ZhB+=f0+f1; AhB+=f0*v0+f1*v1;
        }
        ZhA+=__shfl_xor_sync(0xffffffffu,ZhA,1); ZhA+=__shfl_xor_sync(0xffffffffu,ZhA,2);
        AhA+=__shfl_xor_sync(0xffffffffu,AhA,1); AhA+=__shfl_xor_sync(0xffffffffu,AhA,2);
        ZhB+=__shfl_xor_sync(0xffffffffu,ZhB,1); ZhB+=__shfl_xor_sync(0xffffffffu,ZhB,2);
        AhB+=__shfl_xor_sync(0xffffffffu,AhB,1); AhB+=__shfl_xor_sync(0xffffffffu,AhB,2);
        float nmA=fmaxf(mA,mhA);
        float f1A=fexp((mA-nmA)*sc), f2A=fexp((mhA-nmA)*sc);
        ZA=ZA*f1A+ZhA*f2A; AA=AA*f1A+AhA*f2A; mA=nmA;
        float nmB=fmaxf(mB,mhB);
        float f1B=fexp((mB-nmB)*sc), f2B=fexp((mhB-nmB)*sc);
        ZB=ZB*f1B+ZhB*f2B; AB=AB*f1B+AhB*f2B; mB=nmB;
    }
    if(tg==0){
        int dA=mb+gid, dB=mb+gid+8;
        float attA=AA/ZA, attB=AB/ZB;
        g_sync[b*DM + dA*8 + h]=attA;
        g_sync[b*DM + dB*8 + h]=attB;
        if(outOpt){
            outOpt[b*DM + dA*8 + h]=attA;
            outOpt[b*DM + dB*8 + h]=attB;
        }
    }
}

// ======================= the megakernel =====================================
__global__ void __launch_bounds__(256,2) k_mega(
    const float* __restrict__ beff,
    const float* __restrict__ slns, const float* __restrict__ slnb,
    const float* __restrict__ w1, const float* __restrict__ b1,
    const float* __restrict__ w2, const float* __restrict__ b2,
    const float* __restrict__ outw, const float* __restrict__ outb,
    float* __restrict__ out)
{
    __shared__ float sm[8704];
    unsigned target=0;

    // pre-loop: QKV of initial activation, fill rings, sync_a(0)
    for(int u=blockIdx.x; u<192; u+=NB)
        unit_gemm_tc(g_act, g_Wqkv, g_Pk, nullptr, 3*DM, DM, (u%24)*128, u/24, 8, sm);
    gsync(target);
    for(int u=blockIdx.x; u<512; u+=NB)
        unit_sync(u>>3, u&7, 0, 1, nullptr, sm);
    gsync(target);

    for(int t=0;t<ITERS;t++){
        // P1: cross-Q GEMM (4n x 8z = 32 units)
        for(int u=blockIdx.x; u<32; u+=NB)
            unit_gemm_tc(g_sync, g_Mq, g_Pq, nullptr, DI, DM, (u&3)*128, u>>2, 8, sm);
        gsync(target);
        // P2: cross attention (512 units, exactly 2 rounds)
        for(int u=blockIdx.x; u<512; u+=NB)
            unit_crossatt(u>>3, u&7, beff, g_pre2, sm);
        gsync(target);
        // P3: synapse GEMM (16n x 12z = 192) + output-head GEMM t-1 (8n x 8z = 64)
        int nU3=(t==0)?192:256;
        for(int u=blockIdx.x; u<nU3; u+=NB){
            if(u<192) unit_gemm_tc(g_pre2, g_synw2, g_Ps, nullptr, 2048, 1536, (u&15)*128, u>>4, 8, sm);
            else { int v=u-192; unit_gemm_tc(g_sync, outw, g_Po, nullptr, OUTN, DM, (v&7)*128, v>>3, 8, sm); }
        }
        gsync(target);
        // P4: GLU+LN -> trace slot (64) + pred t-1 (64)
        int nU4=(t==0)?64:128;
        for(int u=blockIdx.x; u<nU4; u+=NB){
            if(u<64) unit_synep(u, slns, slnb, t%MEMN, sm);
            else unit_pred(u-64, outb, out, t-1, sm);
        }
        gsync(target);
        // P5: per-neuron NLM
        for(int u=blockIdx.x; u<256; u+=NB)
            unit_nlm(u, w1, b1, w2, b2, t, sm);
        gsync(target);
        // P6: QKV projection of new activation
        for(int u=blockIdx.x; u<192; u+=NB)
            unit_gemm_tc(g_act, g_Wqkv, g_Pk, nullptr, 3*DM, DM, (u%24)*128, u/24, 8, sm);
        gsync(target);
        // P7: sync attention (tensor-core S + fused softmax + AV)
        for(int u=blockIdx.x; u<512; u+=NB)
            unit_sync(u>>3, u&7, t%MEMN, 0,
                      (t==ITERS-1)?(out+OFF_SYNC):nullptr, sm);
        gsync(target);
    }
    // tail: output head + pred for tick 49
    for(int u=blockIdx.x; u<64; u+=NB)
        unit_gemm_tc(g_sync, outw, g_Po, nullptr, OUTN, DM, (u&7)*128, u>>3, 8, sm);
    gsync(target);
    for(int u=blockIdx.x; u<64; u+=NB)
        unit_pred(u, outb, out, ITERS-1, sm);
}

// ------------------------- host driver -------------------------------------
extern "C" void kernel_launch(void* const* d_in, const int* in_sizes, int n_in,
                              void* d_out, int out_size){
    (void)in_sizes; (void)n_in; (void)out_size;
    const float* x    =(const float*)d_in[0];
    const float* kv_w =(const float*)d_in[1];
    const float* kv_b =(const float*)d_in[2];
    const float* lnks =(const float*)d_in[3];
    const float* lnkb =(const float*)d_in[4];
    const float* q_w  =(const float*)d_in[5];
    const float* q_b  =(const float*)d_in[6];
    const float* inw  =(const float*)d_in[7];
    const float* inb  =(const float*)d_in[8];
    const float* opw  =(const float*)d_in[9];
    const float* opb  =(const float*)d_in[10];
    const float* Wq   =(const float*)d_in[11];
    const float* Wk   =(const float*)d_in[12];
    const float* Wv   =(const float*)d_in[13];
    const float* synw =(const float*)d_in[14];
    const float* synb =(const float*)d_in[15];
    const float* slns =(const float*)d_in[16];
    const float* slnb =(const float*)d_in[17];
    const float* w1   =(const float*)d_in[18];
    const float* b1   =(const float*)d_in[19];
    const float* w2   =(const float*)d_in[20];
    const float* b2   =(const float*)d_in[21];
    const float* sas  =(const float*)d_in[22];
    const float* strc =(const float*)d_in[23];
    const float* outw =(const float*)d_in[24];
    const float* outb =(const float*)d_in[25];
    float* out=(float*)d_out;

    float *p_kv,*p_KV,*p_W,*p_Mq,*p_beff,*p_synw2,*p_bsyn,*p_act,*p_pre2,*p_st;
    unsigned* p_bar;
    cudaGetSymbolAddress((void**)&p_kv,   g_kv);
    cudaGetSymbolAddress((void**)&p_KV,   g_KV);
    cudaGetSymbolAddress((void**)&p_W,    g_Wqkv);
    cudaGetSymbolAddress((void**)&p_Mq,   g_Mq);
    cudaGetSymbolAddress((void**)&p_beff, g_beff);
    cudaGetSymbolAddress((void**)&p_synw2,g_synw2);
    cudaGetSymbolAddress((void**)&p_bsyn, g_bsyn);
    cudaGetSymbolAddress((void**)&p_act,  g_act);
    cudaGetSymbolAddress((void**)&p_pre2, g_pre2);
    cudaGetSymbolAddress((void**)&p_st,   g_st);
    cudaGetSymbolAddress((void**)&p_bar,  g_barCnt);

    // ---- setup: folded weights + KV cache (3xTF32 tensor cores) ----
    k_copyW<<<(3*DM*DM+255)/256,256>>>(Wq,Wk,Wv,p_W);
    k_initact<<<(B_*DM+255)/256,256>>>(sas,p_act,p_pre2);
    k_initst<<<(MEMN*DM*B_+255)/256,256>>>(strc,p_st);
    k_gemm_tc<<<dim3(DI/128,MS/64),256>>>(x,kv_w,p_KV,nullptr,DI,DI);
    k_lnkv<<<MS,256>>>(p_KV,kv_b,lnks,lnkb,p_kv);
    k_gemm_tc<<<dim3(DM/128,MS/64),256>>>(p_kv,inw+(size_t)DI*DI,p_KV,inb+DI,DM,DI);
    k_gemm_tn<<<dim3(DM/64,DI/64),256>>>(inw,q_w,p_Mq,DI,DM,DM,DI,0);
    k_gemm_tn<<<dim3(DI/64,2048/64),256>>>(synw,opw,p_synw2,1536,DI,1536,DI,0);
    k_copyW2<<<(2048*1024+255)/256,256>>>(synw,p_synw2);
    k_bvec<<<2,256>>>(inw,DI,DI,q_b,inb,p_beff,DI);
    k_bvec<<<8,256>>>(synw,1536,DI,opb,synb,p_bsyn,2048);
    // ---- megakernel: all 50 ticks ----
    k_zero<<<1,32>>>(p_bar);
    k_mega<<<NB,256>>>(p_beff,slns,slnb,w1,b1,w2,b2,outw,outb,out);
}